// round 14
// baseline (speedup 1.0000x reference)
#include <cuda_runtime.h>
#include <cstdint>

#define BB   4
#define NN   8192
#define CIN  128
#define COUT 256
#define MM   2048
#define DMID 64
#define KK   16
#define MAXNN 64
#define G8   8
#define CAP  128
#define R2C  0.01f

#define FPT  1024                 // fps threads (8 pts/thread)
#define PPT  (NN / FPT)           // 8
#define PAIRS (PPT / 2)           // 4
#define XPT  512                  // xpre active threads
#define XROWS 32
#define XBLOCKS ((BB * NN) / XROWS)   // 1024
#define CONVBLOCKS ((BB * MM) / G8)   // 1024

// ---------------- scratch (no allocations allowed) ----------------
__device__ int   g_idx[BB][MM];
__device__ float g_xpre[BB][NN][DMID];
__device__ int   g_prog[BB];
__device__ int   g_xdone;

// ---------------- packed f32x2 helpers (bit-identical per lane) ----------------
typedef unsigned long long ull;
__device__ __forceinline__ ull pk2(float a, float b) {
    ull r; asm("mov.b64 %0, {%1, %2};" : "=l"(r) : "f"(a), "f"(b)); return r;
}
__device__ __forceinline__ void upk2(ull v, float& a, float& b) {
    asm("mov.b64 {%0, %1}, %2;" : "=f"(a), "=f"(b) : "l"(v));
}
__device__ __forceinline__ ull add2(ull a, ull b) {
    ull r; asm("add.rn.f32x2 %0, %1, %2;" : "=l"(r) : "l"(a), "l"(b)); return r;
}
__device__ __forceinline__ ull mul2(ull a, ull b) {
    ull r; asm("mul.rn.f32x2 %0, %1, %2;" : "=l"(r) : "l"(a), "l"(b)); return r;
}
__device__ __forceinline__ ull fma2(ull a, ull b, ull c) {
    ull r; asm("fma.rn.f32x2 %0, %1, %2, %3;" : "=l"(r) : "l"(a), "l"(b), "l"(c)); return r;
}
__device__ __forceinline__ unsigned redux_max_u32(unsigned v) {
    unsigned r; asm("redux.sync.max.u32 %0, %1, 0xffffffff;" : "=r"(r) : "r"(v)); return r;
}

// ---------------- init: reset progress flags (fresh every graph replay) ----------------
__global__ void init_kernel() {
    int t = threadIdx.x;
    if (t < BB) g_prog[t] = 0;
    if (t == 0) g_xdone = 0;
}

// ---------------- conv shared layout ----------------
struct ConvSmem {
    int   nlist[G8][CAP];
    float nd2[G8][CAP];
    int   cnt[G8];
    int   nsel[G8];
    int   cpt[G8];
    float ccx[G8], ccy[G8], ccz[G8];
    float kpx[KK], kpy[KK], kpz[KK];
    float relx[MAXNN], rely[MAXNN], relz[MAXNN];
    float xjs[MAXNN][DMID];
    float infl[MAXNN][KK];
    float skd[G8][KK][DMID];
    float xc[G8][CIN];
    float F[G8][DMID];
    float fpart[4][G8][DMID];
};

// ================================================================
// mega kernel: blocks 0..3 FPS | 4..4+XBLOCKS-1 xpre | rest conv
// ================================================================
__global__ __launch_bounds__(FPT, 1) void mega_kernel(
    const float* __restrict__ pos, const float* __restrict__ x,
    const float* __restrict__ Wpre, const float* __restrict__ bpre,
    const float* __restrict__ kp, const float* __restrict__ kpW,
    const float* __restrict__ Wpost, const float* __restrict__ bpost,
    const float* __restrict__ Wsc, const float* __restrict__ bsc,
    float* __restrict__ out_feat, float* __restrict__ out_pos) {
    extern __shared__ __align__(16) float sp[];     // 96KB dynamic
    const int tid = threadIdx.x;

    if (blockIdx.x < BB) {
        // ========== FPS: 1024 threads, 1 redux + 1 atomicMax + 1 barrier ==========
        float* spx = sp;
        float* spy = sp + NN;
        float* spz = sp + 2 * NN;
        __shared__ ull abuf[3];        // rotating argmax accumulators

        const int b = blockIdx.x;
        const float* pb = pos + (size_t)b * NN * 3;

        for (int i = tid; i < NN; i += FPT) {
            spx[i] = pb[3 * i + 0];
            spy[i] = pb[3 * i + 1];
            spz[i] = pb[3 * i + 2];
        }
        if (tid < 3) abuf[tid] = 0ull;
        __syncthreads();

        // register-resident positions: pairs are points (2p)*FPT+tid, (2p+1)*FPT+tid
        ull px2[PAIRS], py2[PAIRS], pz2[PAIRS];
        float md[PPT];
#pragma unroll
        for (int p = 0; p < PAIRS; p++) {
            int i0 = (2 * p) * FPT + tid, i1 = i0 + FPT;
            px2[p] = pk2(spx[i0], spx[i1]);
            py2[p] = pk2(spy[i0], spy[i1]);
            pz2[p] = pk2(spz[i0], spz[i1]);
        }
#pragma unroll
        for (int j = 0; j < PPT; j++) md[j] = 3.4e38f;

        if (tid == 0) g_idx[b][0] = 0;
        float cx = spx[0], cy = spy[0], cz = spz[0];

        for (int t = 1; t < MM; t++) {
            ull ncx = pk2(-cx, -cx), ncy = pk2(-cy, -cy), ncz = pk2(-cz, -cz);
#pragma unroll
            for (int p = 0; p < PAIRS; p++) {
                ull dx = add2(px2[p], ncx);              // exact (p - c)
                ull dy = add2(py2[p], ncy);
                ull dz = add2(pz2[p], ncz);
                ull s  = mul2(dx, dx);
                s = fma2(dy, dy, s);
                s = fma2(dz, dz, s);                     // reference-matched contraction
                float t0, t1; upk2(s, t0, t1);
                md[2 * p]     = fminf(md[2 * p],     t0);
                md[2 * p + 1] = fminf(md[2 * p + 1], t1);
            }
            // local tree max (values >= 0 => float bits order-monotone)
            float x0 = fmaxf(md[0], md[1]), x1 = fmaxf(md[2], md[3]);
            float x2 = fmaxf(md[4], md[5]), x3 = fmaxf(md[6], md[7]);
            float lmax = fmaxf(fmaxf(x0, x1), fmaxf(x2, x3));
            unsigned lb = __float_as_uint(lmax);
            unsigned bw = redux_max_u32(lb);
            if (lb == bw) {
                // owning lane(s): smallest original index holding the warp max
                unsigned best = 0xffffffffu;
#pragma unroll
                for (int j = PPT - 1; j >= 0; j--)       // descending => smallest index kept
                    if (__float_as_uint(md[j]) == bw) best = (unsigned)(j * FPT + tid);
                // key: max value bits, then min original index (8191-best monotone)
                atomicMax(&abuf[t % 3], ((ull)bw << 32) | (ull)(8191u - best));
            }
            __syncthreads();                              // also drains pending ATOMS
            ull win = abuf[t % 3];
            unsigned sel = 8191u - (unsigned)(win & 0xffffffffu);
            cx = spx[sel]; cy = spy[sel]; cz = spz[sel];
            if (tid == 0) {
                g_idx[b][t] = (int)sel;
                abuf[(t + 2) % 3] = 0ull;                 // reset slot used at iter t-1
                if ((t & 15) == 15) { __threadfence(); atomicExch(&g_prog[b], t + 1); }
            }
        }
        if (tid == 0) { __threadfence(); atomicExch(&g_prog[b], MM); }
    } else if (blockIdx.x < BB + XBLOCKS) {
        // ========== x_pre = x @ W_pre + b_pre (512 active) ==========
        if (tid >= XPT) return;
        float* sw = sp;
        float* sx = sp + CIN * DMID;
        const int bx = blockIdx.x - BB;
        const size_t row0 = (size_t)bx * XROWS;

        for (int i = tid; i < CIN * DMID; i += XPT) sw[i] = Wpre[i];
        for (int i = tid; i < XROWS * CIN; i += XPT)
            sx[(i >> 7) * (CIN + 4) + (i & 127)] = x[row0 * CIN + i];
        __syncthreads();

        const int r = tid >> 4, cq = tid & 15;
        float4 acc;
        acc.x = bpre[cq * 4 + 0]; acc.y = bpre[cq * 4 + 1];
        acc.z = bpre[cq * 4 + 2]; acc.w = bpre[cq * 4 + 3];
        const float4* sw4 = reinterpret_cast<const float4*>(sw);
#pragma unroll 8
        for (int k = 0; k < CIN; k++) {
            float  a = sx[r * (CIN + 4) + k];
            float4 w = sw4[k * 16 + cq];
            acc.x = fmaf(a, w.x, acc.x); acc.y = fmaf(a, w.y, acc.y);
            acc.z = fmaf(a, w.z, acc.z); acc.w = fmaf(a, w.w, acc.w);
        }
        float4* dst = reinterpret_cast<float4*>(&g_xpre[0][0][0]);
        dst[(row0 + r) * 16 + cq] = acc;
        __syncthreads();
        if (tid == 0) { __threadfence(); atomicAdd(&g_xdone, 1); }
    } else {
        // ========== conv: 8 centers, 256 active threads ==========
        if (tid >= 256) return;
        ConvSmem& sm = *reinterpret_cast<ConvSmem*>(sp);
        const int bx = blockIdx.x - (BB + XBLOCKS);
        const int b  = bx & 3;
        const int mg = (bx >> 2) * G8;
        const float* pb = pos + (size_t)b * NN * 3;

        if (tid == 0) {
            while (*(volatile int*)&g_xdone < XBLOCKS) __nanosleep(256);
            const int need = mg + G8;
            while (*(volatile int*)&g_prog[b] < need) __nanosleep(256);
            __threadfence();
        }
        __syncthreads();

        if (tid < G8) {
            int pt = g_idx[b][mg + tid];
            sm.cpt[tid] = pt;
            sm.ccx[tid] = pb[3 * pt + 0];
            sm.ccy[tid] = pb[3 * pt + 1];
            sm.ccz[tid] = pb[3 * pt + 2];
            sm.cnt[tid] = 0;
        }
        if (tid < KK) {
            sm.kpx[tid] = kp[3 * tid + 0];
            sm.kpy[tid] = kp[3 * tid + 1];
            sm.kpz[tid] = kp[3 * tid + 2];
        }
        __syncthreads();

        for (int i = tid; i < G8 * CIN; i += 256) {
            int g = i >> 7, ci = i & 127;
            sm.xc[g][ci] = x[((size_t)b * NN + sm.cpt[g]) * CIN + ci];
        }

        ull cx2[G8 / 2], cy2[G8 / 2], cz2[G8 / 2];
#pragma unroll
        for (int gp = 0; gp < G8 / 2; gp++) {
            cx2[gp] = pk2(sm.ccx[2 * gp], sm.ccx[2 * gp + 1]);
            cy2[gp] = pk2(sm.ccy[2 * gp], sm.ccy[2 * gp + 1]);
            cz2[gp] = pk2(sm.ccz[2 * gp], sm.ccz[2 * gp + 1]);
        }

        for (int i = tid; i < NN; i += 256) {
            float px = pb[3 * i + 0], py = pb[3 * i + 1], pz = pb[3 * i + 2];
            ull npx = pk2(-px, -px), npy = pk2(-py, -py), npz = pk2(-pz, -pz);
#pragma unroll
            for (int gp = 0; gp < G8 / 2; gp++) {
                ull dx = add2(cx2[gp], npx);
                ull dy = add2(cy2[gp], npy);
                ull dz = add2(cz2[gp], npz);
                ull s  = mul2(dx, dx);
                s = fma2(dy, dy, s);
                s = fma2(dz, dz, s);
                float d0, d1; upk2(s, d0, d1);
                if (d0 <= R2C) {
                    int p = atomicAdd(&sm.cnt[2 * gp], 1);
                    if (p < CAP) { sm.nlist[2 * gp][p] = i; sm.nd2[2 * gp][p] = d0; }
                }
                if (d1 <= R2C) {
                    int p = atomicAdd(&sm.cnt[2 * gp + 1], 1);
                    if (p < CAP) { sm.nlist[2 * gp + 1][p] = i; sm.nd2[2 * gp + 1][p] = d1; }
                }
            }
        }
        __syncthreads();

        if (tid < G8) {
            int g = tid;
            int c = sm.cnt[g]; if (c > CAP) c = CAP;
            if (c > MAXNN) {
                for (int s = 0; s < MAXNN; s++) {
                    float bvd = 3.4e38f; int bpos = s; int bidx = 0x7fffffff;
                    for (int q = s; q < c; q++) {
                        float v = sm.nd2[g][q]; int ii = sm.nlist[g][q];
                        if (v < bvd || (v == bvd && ii < bidx)) { bvd = v; bpos = q; bidx = ii; }
                    }
                    float tv = sm.nd2[g][s]; int ti = sm.nlist[g][s];
                    sm.nd2[g][s] = bvd;  sm.nlist[g][s] = bidx;
                    sm.nd2[g][bpos] = tv; sm.nlist[g][bpos] = ti;
                }
                c = MAXNN;
            }
            sm.nsel[g] = c;
        }
        __syncthreads();

        for (int g = 0; g < G8; g++) {
            const int ne = sm.nsel[g];
            if (tid < MAXNN && tid < ne) {
                int p = sm.nlist[g][tid];
                sm.relx[tid] = pb[3 * p + 0] - sm.ccx[g];
                sm.rely[tid] = pb[3 * p + 1] - sm.ccy[g];
                sm.relz[tid] = pb[3 * p + 2] - sm.ccz[g];
            }
            for (int i = tid; i < ne * (DMID / 4); i += 256) {
                int e = i >> 4, dq = i & 15;
                const float4* src = reinterpret_cast<const float4*>(&g_xpre[b][sm.nlist[g][e]][0]);
                reinterpret_cast<float4*>(&sm.xjs[e][0])[dq] = src[dq];
            }
            __syncthreads();
            for (int i = tid; i < ne * KK; i += 256) {
                int e = i >> 4, k = i & 15;
                float dx = sm.relx[e] - sm.kpx[k];
                float dy = sm.rely[e] - sm.kpy[k];
                float dz = sm.relz[e] - sm.kpz[k];
                float dd = fmaf(dz, dz, fmaf(dy, dy, dx * dx)) + 1e-12f;
                float dist = sqrtf(dd);
                float v = 1.0f - dist / 0.1f;
                sm.infl[e][k] = v > 0.0f ? v : 0.0f;
            }
            __syncthreads();
            {
                int k = tid >> 4, dq = tid & 15;
                float4 a = make_float4(0.f, 0.f, 0.f, 0.f);
                const float4* xj4 = reinterpret_cast<const float4*>(&sm.xjs[0][0]);
                for (int e = 0; e < ne; e++) {
                    float  f  = sm.infl[e][k];
                    float4 xv = xj4[e * 16 + dq];
                    a.x = fmaf(f, xv.x, a.x); a.y = fmaf(f, xv.y, a.y);
                    a.z = fmaf(f, xv.z, a.z); a.w = fmaf(f, xv.w, a.w);
                }
                reinterpret_cast<float4*>(&sm.skd[g][k][0])[dq] = a;
            }
            __syncthreads();
        }

        {
            int o = tid & 63, p = tid >> 6;
            const float* skdf = &sm.skd[0][0][0];
#pragma unroll
            for (int h = 0; h < 2; h++) {
                float acc[4];
#pragma unroll
                for (int g = 0; g < 4; g++) acc[g] = 0.f;
                for (int kd = p * 256; kd < p * 256 + 256; kd++) {
                    float w = kpW[kd * DMID + o];
#pragma unroll
                    for (int g = 0; g < 4; g++)
                        acc[g] = fmaf(skdf[(h * 4 + g) * 1024 + kd], w, acc[g]);
                }
#pragma unroll
                for (int g = 0; g < 4; g++) sm.fpart[p][h * 4 + g][o] = acc[g];
            }
        }
        __syncthreads();
        for (int i = tid; i < G8 * DMID; i += 256) {
            int g = i >> 6, o = i & 63;
            sm.F[g][o] = sm.fpart[0][g][o] + sm.fpart[1][g][o] + sm.fpart[2][g][o] + sm.fpart[3][g][o];
        }
        __syncthreads();

        {
            int c = tid;
#pragma unroll
            for (int h = 0; h < 2; h++) {
                float acc[4];
                float bb0 = bpost[c] + bsc[c];
#pragma unroll
                for (int g = 0; g < 4; g++) acc[g] = bb0;
                for (int d = 0; d < DMID; d++) {
                    float w = Wpost[d * COUT + c];
#pragma unroll
                    for (int g = 0; g < 4; g++) acc[g] = fmaf(sm.F[h * 4 + g][d], w, acc[g]);
                }
                for (int ci = 0; ci < CIN; ci++) {
                    float w = Wsc[ci * COUT + c];
#pragma unroll
                    for (int g = 0; g < 4; g++) acc[g] = fmaf(sm.xc[h * 4 + g][ci], w, acc[g]);
                }
#pragma unroll
                for (int g = 0; g < 4; g++)
                    out_feat[((size_t)b * MM + mg + h * 4 + g) * COUT + c] = acc[g];
            }
        }
        if (tid < G8 * 3) {
            int g = tid / 3, cc = tid % 3;
            float v = (cc == 0) ? sm.ccx[g] : (cc == 1) ? sm.ccy[g] : sm.ccz[g];
            out_pos[((size_t)b * MM + mg + g) * 3 + cc] = v;
        }
    }
}

// ---------------- launch ----------------
extern "C" void kernel_launch(void* const* d_in, const int* in_sizes, int n_in,
                              void* d_out, int out_size) {
    const float* x     = (const float*)d_in[0];
    const float* pos   = (const float*)d_in[1];
    const float* Wpre  = (const float*)d_in[2];
    const float* bpre  = (const float*)d_in[3];
    const float* kp    = (const float*)d_in[4];
    const float* kpW   = (const float*)d_in[5];
    const float* Wpost = (const float*)d_in[6];
    const float* bpost = (const float*)d_in[7];
    const float* Wsc   = (const float*)d_in[8];
    const float* bsc   = (const float*)d_in[9];

    float* out_feat = (float*)d_out;
    float* out_pos  = out_feat + (size_t)BB * MM * COUT;

    cudaFuncSetAttribute(mega_kernel, cudaFuncAttributeMaxDynamicSharedMemorySize, 3 * NN * 4);

    init_kernel<<<1, 32>>>();
    int grid = BB + XBLOCKS + CONVBLOCKS;   // 4 + 1024 + 1024
    mega_kernel<<<grid, FPT, 3 * NN * 4>>>(
        pos, x, Wpre, bpre, kp, kpW, Wpost, bpost, Wsc, bsc, out_feat, out_pos);
}

// round 15
// speedup vs baseline: 1.2798x; 1.2798x over previous
#include <cuda_runtime.h>
#include <cstdint>

#define BB   4
#define NN   8192
#define CIN  128
#define COUT 256
#define MM   2048
#define DMID 64
#define KK   16
#define MAXNN 64
#define G8   8
#define CAP  128
#define R2C  0.01f

#define FPT  1024                 // fps threads (8 pts/thread)
#define PPT  8
#define XPT  512                  // xpre active threads
#define XROWS 32
#define XBLOCKS ((BB * NN) / XROWS)   // 1024
#define CONVBLOCKS ((BB * MM) / G8)   // 1024

// ---------------- scratch (no allocations allowed) ----------------
__device__ int   g_idx[BB][MM];
__device__ float g_xpre[BB][NN][DMID];
__device__ int   g_sidx[BB][NN];      // sorted slot -> original index
__device__ int   g_prog[BB];
__device__ int   g_xdone;

// ---------------- packed f32x2 helpers (bit-identical per lane) ----------------
typedef unsigned long long ull;
__device__ __forceinline__ ull pk2(float a, float b) {
    ull r; asm("mov.b64 %0, {%1, %2};" : "=l"(r) : "f"(a), "f"(b)); return r;
}
__device__ __forceinline__ void upk2(ull v, float& a, float& b) {
    asm("mov.b64 {%0, %1}, %2;" : "=f"(a), "=f"(b) : "l"(v));
}
__device__ __forceinline__ ull add2(ull a, ull b) {
    ull r; asm("add.rn.f32x2 %0, %1, %2;" : "=l"(r) : "l"(a), "l"(b)); return r;
}
__device__ __forceinline__ ull mul2(ull a, ull b) {
    ull r; asm("mul.rn.f32x2 %0, %1, %2;" : "=l"(r) : "l"(a), "l"(b)); return r;
}
__device__ __forceinline__ ull fma2(ull a, ull b, ull c) {
    ull r; asm("fma.rn.f32x2 %0, %1, %2, %3;" : "=l"(r) : "l"(a), "l"(b), "l"(c)); return r;
}
__device__ __forceinline__ unsigned redux_max_u32(unsigned v) {
    unsigned r; asm("redux.sync.max.u32 %0, %1, 0xffffffff;" : "=r"(r) : "r"(v)); return r;
}
__device__ __forceinline__ int morton3(int kx, int ky, int kz) {
    int m = 0;
    m |= ((kx & 1) << 2) | ((kx & 2) << 4) | ((kx & 4) << 6);
    m |= ((ky & 1) << 1) | ((ky & 2) << 3) | ((ky & 4) << 5);
    m |= ((kz & 1)     ) | ((kz & 2) << 2) | ((kz & 4) << 4);
    return m;
}

// ---------------- init: reset progress flags (fresh every graph replay) ----------------
__global__ void init_kernel() {
    int t = threadIdx.x;
    if (t < BB) g_prog[t] = 0;
    if (t == 0) g_xdone = 0;
}

// ---------------- conv shared layout ----------------
struct ConvSmem {
    int   nlist[G8][CAP];
    float nd2[G8][CAP];
    int   cnt[G8];
    int   nsel[G8];
    int   cpt[G8];
    float ccx[G8], ccy[G8], ccz[G8];
    float kpx[KK], kpy[KK], kpz[KK];
    float relx[MAXNN], rely[MAXNN], relz[MAXNN];
    float xjs[MAXNN][DMID];
    float infl[MAXNN][KK];
    float skd[G8][KK][DMID];
    float xc[G8][CIN];
    float F[G8][DMID];
    float fpart[4][G8][DMID];
};

// ================================================================
// mega kernel: blocks 0..3 FPS | 4..4+XBLOCKS-1 xpre | rest conv
// ================================================================
__global__ __launch_bounds__(FPT, 1) void mega_kernel(
    const float* __restrict__ pos, const float* __restrict__ x,
    const float* __restrict__ Wpre, const float* __restrict__ bpre,
    const float* __restrict__ kp, const float* __restrict__ kpW,
    const float* __restrict__ Wpost, const float* __restrict__ bpost,
    const float* __restrict__ Wsc, const float* __restrict__ bsc,
    float* __restrict__ out_feat, float* __restrict__ out_pos) {
    extern __shared__ __align__(16) float sp[];     // 96KB dynamic
    const int tid = threadIdx.x;

    if (blockIdx.x < BB) {
        // ========== FPS: Morton sort + warp-uniform pruning + R7 tail ==========
        float* spx = sp;
        float* spy = sp + NN;
        float* spz = sp + 2 * NN;
        __shared__ int cntS[512];
        __shared__ int wsum[16];
        __shared__ unsigned swv[32];
        __shared__ float s_c[3];

        const int b = blockIdx.x;
        const int lane = tid & 31, wid = tid >> 5;
        const float* pb = pos + (size_t)b * NN * 3;

        float cx = pb[0], cy = pb[1], cz = pb[2];     // original point 0

        // ---- counting sort into 8x8x8 Morton-ordered cells (R12-proven) ----
        if (tid < 512) cntS[tid] = 0;
        __syncthreads();
        for (int i = tid; i < NN; i += FPT) {
            float xx = pb[3 * i], yy = pb[3 * i + 1], zz = pb[3 * i + 2];
            int kx = min(7, (int)(xx * 8.0f));
            int ky = min(7, (int)(yy * 8.0f));
            int kz = min(7, (int)(zz * 8.0f));
            atomicAdd(&cntS[morton3(kx, ky, kz)], 1);
        }
        __syncthreads();
        int excl = 0, myv = 0;
        if (tid < 512) {
            myv = cntS[tid];
            int xs = myv;
            for (int o = 1; o < 32; o <<= 1) {
                int n = __shfl_up_sync(0xffffffffu, xs, o);
                if (lane >= o) xs += n;
            }
            if (lane == 31) wsum[wid] = xs;
            excl = xs - myv;
        }
        __syncthreads();
        if (tid == 0) {
            int acc = 0;
#pragma unroll
            for (int w = 0; w < 16; w++) { int tv = wsum[w]; wsum[w] = acc; acc += tv; }
        }
        __syncthreads();
        if (tid < 512) excl += wsum[wid];
        __syncthreads();
        if (tid < 512) cntS[tid] = excl;
        __syncthreads();
        for (int i = tid; i < NN; i += FPT) {
            float xx = pb[3 * i], yy = pb[3 * i + 1], zz = pb[3 * i + 2];
            int kx = min(7, (int)(xx * 8.0f));
            int ky = min(7, (int)(yy * 8.0f));
            int kz = min(7, (int)(zz * 8.0f));
            int slot = atomicAdd(&cntS[morton3(kx, ky, kz)], 1);
            spx[slot] = xx; spy[slot] = yy; spz[slot] = zz;
            g_sidx[b][slot] = i;
        }
        __syncthreads();

        // ---- per-thread: 8 consecutive sorted slots (warp = 256 compact points) ----
        const int base = tid * 8;
        ull px2[4], py2[4], pz2[4];
        unsigned op[4];
        float md[PPT];
        float lsx = 0.f, lsy = 0.f, lsz = 0.f;
        {
            float fx[8], fy[8], fz[8];
#pragma unroll
            for (int j = 0; j < 8; j++) {
                fx[j] = spx[base + j]; fy[j] = spy[base + j]; fz[j] = spz[base + j];
                lsx += fx[j]; lsy += fy[j]; lsz += fz[j];
            }
#pragma unroll
            for (int p = 0; p < 4; p++) {
                px2[p] = pk2(fx[2 * p], fx[2 * p + 1]);
                py2[p] = pk2(fy[2 * p], fy[2 * p + 1]);
                pz2[p] = pk2(fz[2 * p], fz[2 * p + 1]);
            }
#pragma unroll
            for (int h = 0; h < 4; h++) {
                unsigned o0 = (unsigned)g_sidx[b][base + 2 * h];
                unsigned o1 = (unsigned)g_sidx[b][base + 2 * h + 1];
                op[h] = o0 | (o1 << 16);
            }
        }
        // warp anchor A = mean of warp's 256 points (shfl tree; all lanes get sum)
#pragma unroll
        for (int o = 16; o > 0; o >>= 1) {
            lsx += __shfl_xor_sync(0xffffffffu, lsx, o);
            lsy += __shfl_xor_sync(0xffffffffu, lsy, o);
            lsz += __shfl_xor_sync(0xffffffffu, lsz, o);
        }
        const float acx = lsx * (1.0f / 256.0f);
        const float acy = lsy * (1.0f / 256.0f);
        const float acz = lsz * (1.0f / 256.0f);
        // warp radius: max dist from A to any warp point (conservative)
        float r2l = 0.f;
#pragma unroll
        for (int j = 0; j < 8; j++) {
            float dx = spx[base + j] - acx;
            float dy = spy[base + j] - acy;
            float dz = spz[base + j] - acz;
            r2l = fmaxf(r2l, fmaf(dz, dz, fmaf(dy, dy, dx * dx)));
        }
        const float RRw = sqrtf(__uint_as_float(redux_max_u32(__float_as_uint(r2l)))) * 1.01f + 1e-6f;

#pragma unroll
        for (int j = 0; j < PPT; j++) md[j] = 3.4e38f;
        unsigned bvt = __float_as_uint(3.4e38f);   // per-thread local max (cached)
        unsigned bw  = __float_as_uint(3.4e38f);   // per-warp max (cached)
        float thr2 = 3.4e38f;                      // prune threshold (cached)

        if (tid == 0) g_idx[b][0] = 0;
        __syncthreads();

        for (int t = 1; t < MM; t++) {
            // warp-uniform prune test (A, RRw, thr2, c identical across lanes)
            float dxa = acx - cx, dya = acy - cy, dza = acz - cz;
            float d2a = fmaf(dza, dza, fmaf(dya, dya, dxa * dxa));
            if (d2a <= thr2) {
                // active warp: exact packed update (reference-matched contraction)
                ull ncx = pk2(-cx, -cx), ncy = pk2(-cy, -cy), ncz = pk2(-cz, -cz);
#pragma unroll
                for (int p = 0; p < 4; p++) {
                    ull dx = add2(px2[p], ncx);
                    ull dy = add2(py2[p], ncy);
                    ull dz = add2(pz2[p], ncz);
                    ull s  = mul2(dx, dx);
                    s = fma2(dy, dy, s);
                    s = fma2(dz, dz, s);
                    float t0, t1; upk2(s, t0, t1);
                    md[2 * p]     = fminf(md[2 * p],     t0);
                    md[2 * p + 1] = fminf(md[2 * p + 1], t1);
                }
                float x0 = fmaxf(md[0], md[1]), x1 = fmaxf(md[2], md[3]);
                float x2 = fmaxf(md[4], md[5]), x3 = fmaxf(md[6], md[7]);
                float lmax = fmaxf(fmaxf(x0, x1), fmaxf(x2, x3));
                bvt = __float_as_uint(lmax);
                bw  = redux_max_u32(bvt);
                // refresh prune threshold (only when bw can change)
                float thr = sqrtf(__uint_as_float(bw)) * 1.01f + RRw;
                thr2 = thr * thr * 1.02f;
            }
            if (lane == 0) swv[wid] = bw;          // cached value when pruned (still valid)
            __syncthreads();
            // block fold (R7 tail): lane-loads + redux; owner writes center+index
            unsigned bm = redux_max_u32(swv[lane]);
            if (bvt == bm) {
                float X = 0.f, Y = 0.f, Z = 0.f;
                unsigned orig = 0u;
                int found = 0;
#pragma unroll
                for (int j = 7; j >= 0; j--) {
                    if (__float_as_uint(md[j]) == bm) {
                        float a0, a1;
                        upk2(px2[j >> 1], a0, a1); X = (j & 1) ? a1 : a0;
                        upk2(py2[j >> 1], a0, a1); Y = (j & 1) ? a1 : a0;
                        upk2(pz2[j >> 1], a0, a1); Z = (j & 1) ? a1 : a0;
                        orig = (op[j >> 1] >> (16 * (j & 1))) & 0xffffu;
                        found = 1;
                    }
                }
                if (found) {
                    s_c[0] = X; s_c[1] = Y; s_c[2] = Z;
                    g_idx[b][t] = (int)orig;
                }
            }
            __syncthreads();
            cx = s_c[0]; cy = s_c[1]; cz = s_c[2];
            if (tid == 0 && (t & 15) == 15) { __threadfence(); atomicExch(&g_prog[b], t + 1); }
        }
        if (tid == 0) { __threadfence(); atomicExch(&g_prog[b], MM); }
    } else if (blockIdx.x < BB + XBLOCKS) {
        // ========== x_pre = x @ W_pre + b_pre (512 active) ==========
        if (tid >= XPT) return;
        float* sw = sp;
        float* sx = sp + CIN * DMID;
        const int bx = blockIdx.x - BB;
        const size_t row0 = (size_t)bx * XROWS;

        for (int i = tid; i < CIN * DMID; i += XPT) sw[i] = Wpre[i];
        for (int i = tid; i < XROWS * CIN; i += XPT)
            sx[(i >> 7) * (CIN + 4) + (i & 127)] = x[row0 * CIN + i];
        __syncthreads();

        const int r = tid >> 4, cq = tid & 15;
        float4 acc;
        acc.x = bpre[cq * 4 + 0]; acc.y = bpre[cq * 4 + 1];
        acc.z = bpre[cq * 4 + 2]; acc.w = bpre[cq * 4 + 3];
        const float4* sw4 = reinterpret_cast<const float4*>(sw);
#pragma unroll 8
        for (int k = 0; k < CIN; k++) {
            float  a = sx[r * (CIN + 4) + k];
            float4 w = sw4[k * 16 + cq];
            acc.x = fmaf(a, w.x, acc.x); acc.y = fmaf(a, w.y, acc.y);
            acc.z = fmaf(a, w.z, acc.z); acc.w = fmaf(a, w.w, acc.w);
        }
        float4* dst = reinterpret_cast<float4*>(&g_xpre[0][0][0]);
        dst[(row0 + r) * 16 + cq] = acc;
        __syncthreads();
        if (tid == 0) { __threadfence(); atomicAdd(&g_xdone, 1); }
    } else {
        // ========== conv: 8 centers, 256 active threads ==========
        if (tid >= 256) return;
        ConvSmem& sm = *reinterpret_cast<ConvSmem*>(sp);
        const int bx = blockIdx.x - (BB + XBLOCKS);
        const int b  = bx & 3;
        const int mg = (bx >> 2) * G8;
        const float* pb = pos + (size_t)b * NN * 3;

        if (tid == 0) {
            while (*(volatile int*)&g_xdone < XBLOCKS) __nanosleep(256);
            const int need = mg + G8;
            while (*(volatile int*)&g_prog[b] < need) __nanosleep(256);
            __threadfence();
        }
        __syncthreads();

        if (tid < G8) {
            int pt = g_idx[b][mg + tid];
            sm.cpt[tid] = pt;
            sm.ccx[tid] = pb[3 * pt + 0];
            sm.ccy[tid] = pb[3 * pt + 1];
            sm.ccz[tid] = pb[3 * pt + 2];
            sm.cnt[tid] = 0;
        }
        if (tid < KK) {
            sm.kpx[tid] = kp[3 * tid + 0];
            sm.kpy[tid] = kp[3 * tid + 1];
            sm.kpz[tid] = kp[3 * tid + 2];
        }
        __syncthreads();

        for (int i = tid; i < G8 * CIN; i += 256) {
            int g = i >> 7, ci = i & 127;
            sm.xc[g][ci] = x[((size_t)b * NN + sm.cpt[g]) * CIN + ci];
        }

        ull cx2[G8 / 2], cy2[G8 / 2], cz2[G8 / 2];
#pragma unroll
        for (int gp = 0; gp < G8 / 2; gp++) {
            cx2[gp] = pk2(sm.ccx[2 * gp], sm.ccx[2 * gp + 1]);
            cy2[gp] = pk2(sm.ccy[2 * gp], sm.ccy[2 * gp + 1]);
            cz2[gp] = pk2(sm.ccz[2 * gp], sm.ccz[2 * gp + 1]);
        }

        for (int i = tid; i < NN; i += 256) {
            float px = pb[3 * i + 0], py = pb[3 * i + 1], pz = pb[3 * i + 2];
            ull npx = pk2(-px, -px), npy = pk2(-py, -py), npz = pk2(-pz, -pz);
#pragma unroll
            for (int gp = 0; gp < G8 / 2; gp++) {
                ull dx = add2(cx2[gp], npx);
                ull dy = add2(cy2[gp], npy);
                ull dz = add2(cz2[gp], npz);
                ull s  = mul2(dx, dx);
                s = fma2(dy, dy, s);
                s = fma2(dz, dz, s);
                float d0, d1; upk2(s, d0, d1);
                if (d0 <= R2C) {
                    int p = atomicAdd(&sm.cnt[2 * gp], 1);
                    if (p < CAP) { sm.nlist[2 * gp][p] = i; sm.nd2[2 * gp][p] = d0; }
                }
                if (d1 <= R2C) {
                    int p = atomicAdd(&sm.cnt[2 * gp + 1], 1);
                    if (p < CAP) { sm.nlist[2 * gp + 1][p] = i; sm.nd2[2 * gp + 1][p] = d1; }
                }
            }
        }
        __syncthreads();

        if (tid < G8) {
            int g = tid;
            int c = sm.cnt[g]; if (c > CAP) c = CAP;
            if (c > MAXNN) {
                for (int s = 0; s < MAXNN; s++) {
                    float bvd = 3.4e38f; int bpos = s; int bidx = 0x7fffffff;
                    for (int q = s; q < c; q++) {
                        float v = sm.nd2[g][q]; int ii = sm.nlist[g][q];
                        if (v < bvd || (v == bvd && ii < bidx)) { bvd = v; bpos = q; bidx = ii; }
                    }
                    float tv = sm.nd2[g][s]; int ti = sm.nlist[g][s];
                    sm.nd2[g][s] = bvd;  sm.nlist[g][s] = bidx;
                    sm.nd2[g][bpos] = tv; sm.nlist[g][bpos] = ti;
                }
                c = MAXNN;
            }
            sm.nsel[g] = c;
        }
        __syncthreads();

        for (int g = 0; g < G8; g++) {
            const int ne = sm.nsel[g];
            if (tid < MAXNN && tid < ne) {
                int p = sm.nlist[g][tid];
                sm.relx[tid] = pb[3 * p + 0] - sm.ccx[g];
                sm.rely[tid] = pb[3 * p + 1] - sm.ccy[g];
                sm.relz[tid] = pb[3 * p + 2] - sm.ccz[g];
            }
            for (int i = tid; i < ne * (DMID / 4); i += 256) {
                int e = i >> 4, dq = i & 15;
                const float4* src = reinterpret_cast<const float4*>(&g_xpre[b][sm.nlist[g][e]][0]);
                reinterpret_cast<float4*>(&sm.xjs[e][0])[dq] = src[dq];
            }
            __syncthreads();
            for (int i = tid; i < ne * KK; i += 256) {
                int e = i >> 4, k = i & 15;
                float dx = sm.relx[e] - sm.kpx[k];
                float dy = sm.rely[e] - sm.kpy[k];
                float dz = sm.relz[e] - sm.kpz[k];
                float dd = fmaf(dz, dz, fmaf(dy, dy, dx * dx)) + 1e-12f;
                float dist = sqrtf(dd);
                float v = 1.0f - dist / 0.1f;
                sm.infl[e][k] = v > 0.0f ? v : 0.0f;
            }
            __syncthreads();
            {
                int k = tid >> 4, dq = tid & 15;
                float4 a = make_float4(0.f, 0.f, 0.f, 0.f);
                const float4* xj4 = reinterpret_cast<const float4*>(&sm.xjs[0][0]);
                for (int e = 0; e < ne; e++) {
                    float  f  = sm.infl[e][k];
                    float4 xv = xj4[e * 16 + dq];
                    a.x = fmaf(f, xv.x, a.x); a.y = fmaf(f, xv.y, a.y);
                    a.z = fmaf(f, xv.z, a.z); a.w = fmaf(f, xv.w, a.w);
                }
                reinterpret_cast<float4*>(&sm.skd[g][k][0])[dq] = a;
            }
            __syncthreads();
        }

        {
            int o = tid & 63, p = tid >> 6;
            const float* skdf = &sm.skd[0][0][0];
#pragma unroll
            for (int h = 0; h < 2; h++) {
                float acc[4];
#pragma unroll
                for (int g = 0; g < 4; g++) acc[g] = 0.f;
                for (int kd = p * 256; kd < p * 256 + 256; kd++) {
                    float w = kpW[kd * DMID + o];
#pragma unroll
                    for (int g = 0; g < 4; g++)
                        acc[g] = fmaf(skdf[(h * 4 + g) * 1024 + kd], w, acc[g]);
                }
#pragma unroll
                for (int g = 0; g < 4; g++) sm.fpart[p][h * 4 + g][o] = acc[g];
            }
        }
        __syncthreads();
        for (int i = tid; i < G8 * DMID; i += 256) {
            int g = i >> 6, o = i & 63;
            sm.F[g][o] = sm.fpart[0][g][o] + sm.fpart[1][g][o] + sm.fpart[2][g][o] + sm.fpart[3][g][o];
        }
        __syncthreads();

        {
            int c = tid;
#pragma unroll
            for (int h = 0; h < 2; h++) {
                float acc[4];
                float bb0 = bpost[c] + bsc[c];
#pragma unroll
                for (int g = 0; g < 4; g++) acc[g] = bb0;
                for (int d = 0; d < DMID; d++) {
                    float w = Wpost[d * COUT + c];
#pragma unroll
                    for (int g = 0; g < 4; g++) acc[g] = fmaf(sm.F[h * 4 + g][d], w, acc[g]);
                }
                for (int ci = 0; ci < CIN; ci++) {
                    float w = Wsc[ci * COUT + c];
#pragma unroll
                    for (int g = 0; g < 4; g++) acc[g] = fmaf(sm.xc[h * 4 + g][ci], w, acc[g]);
                }
#pragma unroll
                for (int g = 0; g < 4; g++)
                    out_feat[((size_t)b * MM + mg + h * 4 + g) * COUT + c] = acc[g];
            }
        }
        if (tid < G8 * 3) {
            int g = tid / 3, cc = tid % 3;
            float v = (cc == 0) ? sm.ccx[g] : (cc == 1) ? sm.ccy[g] : sm.ccz[g];
            out_pos[((size_t)b * MM + mg + g) * 3 + cc] = v;
        }
    }
}

// ---------------- launch ----------------
extern "C" void kernel_launch(void* const* d_in, const int* in_sizes, int n_in,
                              void* d_out, int out_size) {
    const float* x     = (const float*)d_in[0];
    const float* pos   = (const float*)d_in[1];
    const float* Wpre  = (const float*)d_in[2];
    const float* bpre  = (const float*)d_in[3];
    const float* kp    = (const float*)d_in[4];
    const float* kpW   = (const float*)d_in[5];
    const float* Wpost = (const float*)d_in[6];
    const float* bpost = (const float*)d_in[7];
    const float* Wsc   = (const float*)d_in[8];
    const float* bsc   = (const float*)d_in[9];

    float* out_feat = (float*)d_out;
    float* out_pos  = out_feat + (size_t)BB * MM * COUT;

    cudaFuncSetAttribute(mega_kernel, cudaFuncAttributeMaxDynamicSharedMemorySize, 3 * NN * 4);

    init_kernel<<<1, 32>>>();
    int grid = BB + XBLOCKS + CONVBLOCKS;   // 4 + 1024 + 1024
    mega_kernel<<<grid, FPT, 3 * NN * 4>>>(
        pos, x, Wpre, bpre, kp, kpW, Wpost, bpost, Wsc, bsc, out_feat, out_pos);
}